// round 1
// baseline (speedup 1.0000x reference)
#include <cuda_runtime.h>
#include <math.h>

// Problem constants
#define BB 128
#define NN 49
#define CC 2048
#define DD 512
#define EE 512
#define VV 10000
#define TT 20
#define XDIM 1536      // D + E + D  (x=[vg,we] 1024, plus h 512)
#define GDIM 2560      // 4D gates + D gate-linear

// ---------------- device scratch (static, allowed) ----------------
__device__ float g_mean[BB * CC];
__device__ float g_vghm[BB * 1536];          // [vg | h0 | m0] per row
__device__ float g_Vf[BB * NN * DD];
__device__ float g_zbase[BB * NN * NN];
__device__ float g_xall[(size_t)TT * BB * XDIM];
__device__ float g_Wcat[GDIM * XDIM];
__device__ float g_bcat[GDIM];
__device__ float g_preact[BB * GDIM];
__device__ float g_h[2][BB * DD];
__device__ float g_m[2][BB * DD];
__device__ float g_u[BB * DD];
__device__ float g_Hb[BB * DD];
__device__ float g_sb[BB * DD];
__device__ float g_t1[BB * DD];
__device__ float g_o512[BB * DD];

__device__ __forceinline__ float sigf(float x) { return 1.0f / (1.0f + expf(-x)); }

// ---------------- generic GEMM: C = act(A[M,K] * W[N,K]^T + bias) ----------------
// 64x64 tile, 256 threads, 4x4 per thread, BK=16. K must be multiple of 16.
template <int ACT>  // 0 none, 1 relu, 2 tanh
__global__ void gemm_k(const float* __restrict__ A, int lda,
                       const float* __restrict__ W, int ldw,
                       const float* __restrict__ bias,
                       float* __restrict__ C, long long ldc,
                       int M, int N, int K)
{
    __shared__ float sA[16][65];
    __shared__ float sW[16][65];
    const int tid = threadIdx.x;
    const int tx = tid & 15, ty = tid >> 4;
    const int m0 = blockIdx.y * 64, n0 = blockIdx.x * 64;
    float acc[4][4];
#pragma unroll
    for (int i = 0; i < 4; i++)
#pragma unroll
        for (int j = 0; j < 4; j++) acc[i][j] = 0.f;

    for (int k0 = 0; k0 < K; k0 += 16) {
#pragma unroll
        for (int e = 0; e < 4; e++) {
            int q = tid + 256 * e;
            int r = q >> 4, c = q & 15;
            int row = m0 + r;
            float va = 0.f;
            if (row < M) va = A[(size_t)row * lda + k0 + c];
            sA[c][r] = va;
            int n = n0 + r;
            float vw = 0.f;
            if (n < N) vw = W[(size_t)n * ldw + k0 + c];
            sW[c][r] = vw;
        }
        __syncthreads();
#pragma unroll
        for (int k = 0; k < 16; k++) {
            float a[4], b[4];
#pragma unroll
            for (int i = 0; i < 4; i++) a[i] = sA[k][ty * 4 + i];
#pragma unroll
            for (int j = 0; j < 4; j++) b[j] = sW[k][tx * 4 + j];
#pragma unroll
            for (int i = 0; i < 4; i++)
#pragma unroll
                for (int j = 0; j < 4; j++) acc[i][j] = fmaf(a[i], b[j], acc[i][j]);
        }
        __syncthreads();
    }
#pragma unroll
    for (int i = 0; i < 4; i++) {
        int row = m0 + ty * 4 + i;
        if (row >= M) continue;
#pragma unroll
        for (int j = 0; j < 4; j++) {
            int col = n0 + tx * 4 + j;
            if (col >= N) continue;
            float v = acc[i][j];
            if (bias) v += bias[col];
            if (ACT == 1) v = fmaxf(v, 0.f);
            else if (ACT == 2) v = tanhf(v);
            C[(size_t)row * ldc + col] = v;
        }
    }
}

// ---------------- small kernels ----------------
__global__ void mean_kernel(const float* __restrict__ img)
{
    int idx = blockIdx.x * blockDim.x + threadIdx.x;
    if (idx >= BB * CC) return;
    int b = idx / CC, c = idx % CC;
    const float* p = img + (size_t)b * NN * CC + c;
    float s = 0.f;
#pragma unroll 7
    for (int n = 0; n < NN; n++) s += p[(size_t)n * CC];
    g_mean[idx] = s * (1.0f / NN);
}

__global__ void hm_init_kernel()
{
    int idx = blockIdx.x * blockDim.x + threadIdx.x;
    if (idx >= BB * DD) return;
    int b = idx >> 9, d = idx & 511;
    g_h[0][idx] = g_vghm[b * 1536 + 512 + d];
    g_m[0][idx] = g_vghm[b * 1536 + 1024 + d];
}

__global__ void xall_init_kernel(const float* __restrict__ emb, const int* __restrict__ target)
{
    int idx = blockIdx.x * blockDim.x + threadIdx.x;
    if (idx >= TT * BB * 1024) return;
    int j = idx % 1024;
    int tb = idx / 1024;
    int b = tb % BB;
    int t = tb / BB;
    float v;
    if (j < 512) {
        v = g_vghm[b * 1536 + j];           // vg
    } else {
        if (t == 0) v = 0.f;
        else {
            int tok = target[b * TT + t - 1];
            v = emb[(size_t)tok * EE + (j - 512)];
        }
    }
    g_xall[((size_t)t * BB + b) * XDIM + j] = v;
}

__global__ void build_wcat_kernel(const float* __restrict__ Wih, const float* __restrict__ Whh,
                                  const float* __restrict__ Wx, const float* __restrict__ Wh2,
                                  const float* __restrict__ bih, const float* __restrict__ bhh)
{
    int idx = blockIdx.x * blockDim.x + threadIdx.x;
    if (idx >= GDIM * XDIM) return;
    int r = idx / XDIM, c = idx % XDIM;
    float v;
    if (r < 2048) v = (c < 1024) ? Wih[(size_t)r * 1024 + c] : Whh[(size_t)r * 512 + (c - 1024)];
    else {
        int r2 = r - 2048;
        v = (c < 1024) ? Wx[(size_t)r2 * 1024 + c] : Wh2[(size_t)r2 * 512 + (c - 1024)];
    }
    g_Wcat[idx] = v;
    if (c == 0) g_bcat[r] = (r < 2048) ? (bih[r] + bhh[r]) : 0.f;
}

__global__ void copy_h_kernel(int t, int cur)
{
    int idx = blockIdx.x * blockDim.x + threadIdx.x;
    if (idx >= BB * DD) return;
    int b = idx >> 9, d = idx & 511;
    g_xall[((size_t)t * BB + b) * XDIM + 1024 + d] = g_h[cur][idx];
}

__global__ void lstm_elem_kernel(int cur, int nxt)
{
    int idx = blockIdx.x * blockDim.x + threadIdx.x;
    if (idx >= BB * DD) return;
    int b = idx >> 9, d = idx & 511;
    const float* p = g_preact + (size_t)b * GDIM;
    float gi = p[d], gf = p[512 + d], gg = p[1024 + d], go = p[1536 + d], gl = p[2048 + d];
    float m2 = sigf(gf) * g_m[cur][idx] + sigf(gi) * tanhf(gg);
    float tm2 = tanhf(m2);
    float h2 = sigf(go) * tm2;
    g_m[nxt][idx] = m2;
    g_h[nxt][idx] = h2;
    g_u[idx] = sigf(gl) * tm2;   // gt * tanh(m2)
}

// fused: gH = H@Wg^T, sWs = s@Ws^T, z, z2, softmax(50), attn out, ctx, t1=H+ctx
__global__ void attn_fused_kernel(const float* __restrict__ Wg, const float* __restrict__ Wsm,
                                  const float* __restrict__ wh,
                                  float* __restrict__ attn_out, int t)
{
    int b = blockIdx.x;
    __shared__ float sH[512], sS[512];
    __shared__ float gHs[49], sWss[49], zsh[50], wsh[49];
    int tid = threadIdx.x;  // 256
    for (int j = tid; j < 512; j += 256) {
        sH[j] = g_Hb[b * 512 + j];
        sS[j] = g_sb[b * 512 + j];
    }
    if (tid < 49) wsh[tid] = wh[tid];
    __syncthreads();

    int w = tid >> 5, lane = tid & 31;
    for (int n = w; n < 49; n += 8) {
        float a = 0.f, c = 0.f;
        const float* wg = Wg + (size_t)n * 512;
        const float* ws = Wsm + (size_t)n * 512;
        for (int d = lane; d < 512; d += 32) {
            a = fmaf(sH[d], wg[d], a);
            c = fmaf(sS[d], ws[d], c);
        }
#pragma unroll
        for (int off = 16; off; off >>= 1) {
            a += __shfl_down_sync(0xffffffffu, a, off);
            c += __shfl_down_sync(0xffffffffu, c, off);
        }
        if (lane == 0) { gHs[n] = a; sWss[n] = c; }
    }
    __syncthreads();

    if (tid < 49) {
        const float* zb = g_zbase + ((size_t)b * 49 + tid) * 49;
        float acc = 0.f;
#pragma unroll 7
        for (int k = 0; k < 49; k++) acc += tanhf(zb[k] + gHs[k]) * wsh[k];
        zsh[tid] = acc;
    } else if (tid == 49) {
        float acc = 0.f;
#pragma unroll 7
        for (int k = 0; k < 49; k++) acc += tanhf(sWss[k] + gHs[k]) * wsh[k];
        zsh[49] = acc;
    }
    __syncthreads();

    if (tid == 0) {
        float mx = -1e30f;
        for (int i = 0; i < 50; i++) mx = fmaxf(mx, zsh[i]);
        float sum = 0.f;
        for (int i = 0; i < 50; i++) { zsh[i] = expf(zsh[i] - mx); sum += zsh[i]; }
        float inv = 1.f / sum;
        for (int i = 0; i < 50; i++) zsh[i] *= inv;
    }
    __syncthreads();

    if (tid < 49) attn_out[((size_t)b * TT + t) * 49 + tid] = zsh[tid];

    float a50 = zsh[49];
    for (int d = tid; d < 512; d += 256) {
        float acc = a50 * sS[d];
#pragma unroll 7
        for (int n = 0; n < 49; n++)
            acc = fmaf(zsh[n], g_Vf[((size_t)b * 49 + n) * 512 + d], acc);
        g_t1[b * 512 + d] = sH[d] + acc;
    }
}

__global__ void log_softmax_kernel(float* __restrict__ logits)
{
    int row = blockIdx.x;  // B*T rows
    float* x = logits + (size_t)row * VV;
    __shared__ float red[256];
    int tid = threadIdx.x;
    float mx = -1e30f;
    for (int i = tid; i < VV; i += 256) mx = fmaxf(mx, x[i]);
    red[tid] = mx; __syncthreads();
    for (int s = 128; s; s >>= 1) { if (tid < s) red[tid] = fmaxf(red[tid], red[tid + s]); __syncthreads(); }
    mx = red[0];
    __syncthreads();
    float sum = 0.f;
    for (int i = tid; i < VV; i += 256) sum += expf(x[i] - mx);
    red[tid] = sum; __syncthreads();
    for (int s = 128; s; s >>= 1) { if (tid < s) red[tid] += red[tid + s]; __syncthreads(); }
    float lse = mx + logf(red[0]);
    for (int i = tid; i < VV; i += 256) x[i] -= lse;
}

// ---------------- host ----------------
static inline dim3 ggrid(int M, int N) { return dim3((N + 63) / 64, (M + 63) / 64); }

extern "C" void kernel_launch(void* const* d_in, const int* in_sizes, int n_in,
                              void* d_out, int out_size)
{
    const float* img    = (const float*)d_in[0];
    const int*   target = (const int*)d_in[1];
    const float* emb    = (const float*)d_in[2];
    const float* Wa  = (const float*)d_in[3];  const float* ba  = (const float*)d_in[4];
    const float* Wb  = (const float*)d_in[5];  const float* bb  = (const float*)d_in[6];
    const float* Whi = (const float*)d_in[7];  const float* bhi = (const float*)d_in[8];
    const float* Wmi = (const float*)d_in[9];  const float* bmi = (const float*)d_in[10];
    const float* Wih = (const float*)d_in[11]; const float* bih = (const float*)d_in[12];
    const float* Whh = (const float*)d_in[13]; const float* bhh = (const float*)d_in[14];
    const float* Wv  = (const float*)d_in[15];
    const float* Wg  = (const float*)d_in[16];
    const float* wh  = (const float*)d_in[17];
    const float* WH  = (const float*)d_in[18];
    const float* Wx  = (const float*)d_in[19];
    const float* Wh2 = (const float*)d_in[20];
    const float* Wsm = (const float*)d_in[21];
    const float* Wc  = (const float*)d_in[22]; const float* bc  = (const float*)d_in[23];
    const float* Wfc = (const float*)d_in[24]; const float* bfc = (const float*)d_in[25];
    const float* Wp  = (const float*)d_in[26]; const float* bp  = (const float*)d_in[27];

    float* out_logits = (float*)d_out;                               // [B,T,VOC]
    float* out_attn   = (float*)d_out + (size_t)BB * TT * VV;        // [B,T,N]

    // scratch addresses
    float *p_mean, *p_vghm, *p_Vf, *p_zbase, *p_xall, *p_Wcat, *p_bcat, *p_preact;
    float *p_h, *p_m, *p_u, *p_H, *p_s, *p_t1, *p_o512;
    cudaGetSymbolAddress((void**)&p_mean,  g_mean);
    cudaGetSymbolAddress((void**)&p_vghm,  g_vghm);
    cudaGetSymbolAddress((void**)&p_Vf,    g_Vf);
    cudaGetSymbolAddress((void**)&p_zbase, g_zbase);
    cudaGetSymbolAddress((void**)&p_xall,  g_xall);
    cudaGetSymbolAddress((void**)&p_Wcat,  g_Wcat);
    cudaGetSymbolAddress((void**)&p_bcat,  g_bcat);
    cudaGetSymbolAddress((void**)&p_preact,g_preact);
    cudaGetSymbolAddress((void**)&p_h,     g_h);
    cudaGetSymbolAddress((void**)&p_m,     g_m);
    cudaGetSymbolAddress((void**)&p_u,     g_u);
    cudaGetSymbolAddress((void**)&p_H,     g_Hb);
    cudaGetSymbolAddress((void**)&p_s,     g_sb);
    cudaGetSymbolAddress((void**)&p_t1,    g_t1);
    cudaGetSymbolAddress((void**)&p_o512,  g_o512);

    // ---- precompute ----
    mean_kernel<<<(BB * CC + 255) / 256, 256>>>(img);
    // vg | h0 | m0 into g_vghm (ldc=1536)
    gemm_k<1><<<ggrid(BB, DD), 256>>>(p_mean, CC, Wb,  CC, bb,  p_vghm + 0,    1536, BB, DD, CC);
    gemm_k<1><<<ggrid(BB, DD), 256>>>(p_mean, CC, Whi, CC, bhi, p_vghm + 512,  1536, BB, DD, CC);
    gemm_k<1><<<ggrid(BB, DD), 256>>>(p_mean, CC, Wmi, CC, bmi, p_vghm + 1024, 1536, BB, DD, CC);
    hm_init_kernel<<<(BB * DD + 255) / 256, 256>>>();
    // Vf = relu(img @ Wa^T + ba)
    gemm_k<1><<<ggrid(BB * NN, DD), 256>>>(img, CC, Wa, CC, ba, p_Vf, DD, BB * NN, DD, CC);
    // zbase = Vf @ Wv^T
    gemm_k<0><<<ggrid(BB * NN, NN), 256>>>(p_Vf, DD, Wv, DD, nullptr, p_zbase, NN, BB * NN, NN, DD);
    // x buffers for every t (vg + shifted embedding)
    xall_init_kernel<<<(TT * BB * 1024 + 255) / 256, 256>>>(emb, target);
    // concatenated gate weight
    build_wcat_kernel<<<(GDIM * XDIM + 255) / 256, 256>>>(Wih, Whh, Wx, Wh2, bih, bhh);

    // ---- timestep loop ----
    for (int t = 0; t < TT; t++) {
        int cur = t & 1, nxt = cur ^ 1;
        copy_h_kernel<<<(BB * DD + 255) / 256, 256>>>(t, cur);
        // preact[B,2560] = xh_t @ Wcat^T + bcat
        gemm_k<0><<<ggrid(BB, GDIM), 256>>>(p_xall + (size_t)t * BB * XDIM, XDIM,
                                            p_Wcat, XDIM, p_bcat, p_preact, GDIM, BB, GDIM, XDIM);
        lstm_elem_kernel<<<(BB * DD + 255) / 256, 256>>>(cur, nxt);
        // H = relu(h2 @ WH^T)   (no bias)
        gemm_k<1><<<ggrid(BB, DD), 256>>>(p_h + (size_t)nxt * BB * DD, DD, WH, DD, nullptr, p_H, DD, BB, DD, DD);
        // s = relu(u @ Wc^T + bc)
        gemm_k<1><<<ggrid(BB, DD), 256>>>(p_u, DD, Wc, DD, bc, p_s, DD, BB, DD, DD);
        // attention + context + t1 = H + ctx
        attn_fused_kernel<<<BB, 256>>>(Wg, Wsm, wh, out_attn, t);
        // out = tanh(t1 @ Wfc^T + bfc)
        gemm_k<2><<<ggrid(BB, DD), 256>>>(p_t1, DD, Wfc, DD, bfc, p_o512, DD, BB, DD, DD);
        // logits into d_out at [:, t, :], row stride T*VOC
        gemm_k<0><<<ggrid(BB, VV), 256>>>(p_o512, DD, Wp, DD, bp,
                                          out_logits + (size_t)t * VV, (long long)TT * VV, BB, VV, DD);
    }

    // in-place log_softmax over all B*T rows
    log_softmax_kernel<<<BB * TT, 256>>>(out_logits);
}

// round 2
// speedup vs baseline: 2.5179x; 2.5179x over previous
#include <cuda_runtime.h>
#include <math.h>

// Problem constants
#define BB 128
#define NN 49
#define CC 2048
#define DD 512
#define EE 512
#define VV 10000
#define TT 20
#define XD1 1024       // x = [vg | we]
#define XDIM 1536      // x plus h
#define GDIM 2560      // 4D gates + D gate-linear
#define SKP 4          // split-K factor for per-step GEMMs

typedef unsigned long long ull;

// ---------------- device scratch ----------------
__device__ __align__(16) float g_mean[BB * CC];
__device__ __align__(16) float g_vghm[BB * 1536];
__device__ __align__(16) float g_Vf[BB * NN * DD];
__device__ __align__(16) float g_zbase[BB * NN * NN];
__device__ __align__(16) float g_xall[TT * BB * XD1];
__device__ __align__(16) float g_Wcat[GDIM * XDIM];
__device__ __align__(16) float g_bcat[GDIM];
__device__ __align__(16) float g_Wbhm[1536 * CC];
__device__ __align__(16) float g_bbhm[1536];
__device__ __align__(16) float g_pre_part[SKP][BB * GDIM];
__device__ __align__(16) float g_hs_part[2 * SKP][BB * DD];
__device__ __align__(16) float g_fc_part[SKP][BB * DD];
__device__ __align__(16) float g_h[2][BB * DD];
__device__ __align__(16) float g_m[2][BB * DD];
__device__ __align__(16) float g_u[BB * DD];
__device__ __align__(16) float g_t1[BB * DD];
__device__ __align__(16) float g_o512[BB * DD];

__device__ __forceinline__ float sigf(float x) { return 1.0f / (1.0f + expf(-x)); }

// ---------------- packed f32x2 helpers ----------------
__device__ __forceinline__ ull packbb(float x, float y) {
    ull r; asm("mov.b64 %0, {%1, %2};" : "=l"(r) : "f"(x), "f"(y)); return r;
}
__device__ __forceinline__ void ffma2(ull& d, ull a, ull b) {
    asm("fma.rn.f32x2 %0, %1, %2, %0;" : "+l"(d) : "l"(a), "l"(b));
}
__device__ __forceinline__ float2 unpk(ull v) {
    float2 f; asm("mov.b64 {%0, %1}, %2;" : "=f"(f.x), "=f"(f.y) : "l"(v)); return f;
}

// 16-k MMA over a 64x64 tile: 4 rows x 4 cols per thread, f32x2 packed
__device__ __forceinline__ void tile_mma(const float (&sA)[16][68], const float (&sW)[16][68],
                                         int ty4, int tx4, ull (&acc)[4][2])
{
#pragma unroll
    for (int kk = 0; kk < 16; kk++) {
        float4 av = *reinterpret_cast<const float4*>(&sA[kk][ty4]);
        ulonglong2 bv = *reinterpret_cast<const ulonglong2*>(&sW[kk][tx4]);
        ull am;
        am = packbb(av.x, av.x); ffma2(acc[0][0], am, bv.x); ffma2(acc[0][1], am, bv.y);
        am = packbb(av.y, av.y); ffma2(acc[1][0], am, bv.x); ffma2(acc[1][1], am, bv.y);
        am = packbb(av.z, av.z); ffma2(acc[2][0], am, bv.x); ffma2(acc[2][1], am, bv.y);
        am = packbb(av.w, av.w); ffma2(acc[3][0], am, bv.x); ffma2(acc[3][1], am, bv.y);
    }
}

#define TILE_DECL \
    __shared__ __align__(16) float sA[16][68]; \
    __shared__ __align__(16) float sW[16][68]; \
    const int tid = threadIdx.x; \
    const int tx4 = (tid & 15) * 4; \
    const int ty4 = (tid >> 4) * 4; \
    const int lr = tid >> 2, lc = (tid & 3) * 4; \
    ull acc[4][2]; \
    acc[0][0]=0ULL;acc[0][1]=0ULL;acc[1][0]=0ULL;acc[1][1]=0ULL; \
    acc[2][0]=0ULL;acc[2][1]=0ULL;acc[3][0]=0ULL;acc[3][1]=0ULL;

#define STORE_A(va) { sA[lc][lr]=va.x; sA[lc+1][lr]=va.y; sA[lc+2][lr]=va.z; sA[lc+3][lr]=va.w; }
#define STORE_W(vw) { sW[lc][lr]=vw.x; sW[lc+1][lr]=vw.y; sW[lc+2][lr]=vw.z; sW[lc+3][lr]=vw.w; }

// ---------------- full GEMM: C = act(A[M,K] @ W[N,K]^T + bias) ----------------
template <int ACT>  // 0 none, 1 relu, 2 tanh
__global__ void gemm_act(const float* __restrict__ A, int lda,
                         const float* __restrict__ W, int ldw,
                         const float* __restrict__ bias,
                         float* __restrict__ C, long long ldc,
                         int M, int N, int K)
{
    TILE_DECL;
    const int m0 = blockIdx.y * 64, n0 = blockIdx.x * 64;
    const int arow = m0 + lr, wrow = n0 + lr;
    const float4 z4 = make_float4(0.f, 0.f, 0.f, 0.f);
    for (int k0 = 0; k0 < K; k0 += 16) {
        float4 va = z4, vw = z4;
        if (arow < M) va = *reinterpret_cast<const float4*>(A + (size_t)arow * lda + k0 + lc);
        if (wrow < N) vw = *reinterpret_cast<const float4*>(W + (size_t)wrow * ldw + k0 + lc);
        STORE_A(va); STORE_W(vw);
        __syncthreads();
        tile_mma(sA, sW, ty4, tx4, acc);
        __syncthreads();
    }
#pragma unroll
    for (int i = 0; i < 4; i++) {
        int row = m0 + ty4 + i;
        if (row >= M) continue;
        float2 v0 = unpk(acc[i][0]), v1 = unpk(acc[i][1]);
        float vv[4] = { v0.x, v0.y, v1.x, v1.y };
#pragma unroll
        for (int j = 0; j < 4; j++) {
            int col = n0 + tx4 + j;
            if (col >= N) continue;
            float v = vv[j];
            if (bias) v += bias[col];
            if (ACT == 1) v = fmaxf(v, 0.f);
            else if (ACT == 2) v = tanhf(v);
            C[(size_t)row * ldc + col] = v;
        }
    }
}

// ---------------- split-K GEMM, A/W selected by blockIdx.z/skn (M=128,N=512,K=512) ----------------
__global__ void gemm_sksel(const float* __restrict__ A0, const float* __restrict__ A1,
                           const float* __restrict__ W0, const float* __restrict__ W1,
                           float* __restrict__ Cpart, int skn)
{
    TILE_DECL;
    const int sk = blockIdx.z % skn, which = blockIdx.z / skn;
    const float* A = which ? A1 : A0;
    const float* W = which ? W1 : W0;
    const int Ksl = 512 / skn;
    const int m0 = blockIdx.y * 64, n0 = blockIdx.x * 64;
    const float* Ap = A + (size_t)(m0 + lr) * 512 + sk * Ksl + lc;
    const float* Wq = W + (size_t)(n0 + lr) * 512 + sk * Ksl + lc;
    for (int k0 = 0; k0 < Ksl; k0 += 16) {
        float4 va = *reinterpret_cast<const float4*>(Ap + k0);
        float4 vw = *reinterpret_cast<const float4*>(Wq + k0);
        STORE_A(va); STORE_W(vw);
        __syncthreads();
        tile_mma(sA, sW, ty4, tx4, acc);
        __syncthreads();
    }
    float* Cz = Cpart + (size_t)blockIdx.z * (128 * 512);
#pragma unroll
    for (int i = 0; i < 4; i++) {
        int row = m0 + ty4 + i;
        float2 v0 = unpk(acc[i][0]), v1 = unpk(acc[i][1]);
        *reinterpret_cast<float4*>(Cz + (size_t)row * 512 + n0 + tx4) =
            make_float4(v0.x, v0.y, v1.x, v1.y);
    }
}

// ---------------- split-K preact GEMM: A = [X | Hc], W = Wcat (M=128,N=2560,K=1536) ----------------
__global__ void gemm_preact(const float* __restrict__ X, const float* __restrict__ Hc,
                            float* __restrict__ Cpart)
{
    TILE_DECL;
    const int sk = blockIdx.z;
    const int Ksl = XDIM / SKP;   // 384
    const int kb = sk * Ksl;
    const int m0 = blockIdx.y * 64, n0 = blockIdx.x * 64;
    const int arow = m0 + lr, wrow = n0 + lr;
    for (int k0 = 0; k0 < Ksl; k0 += 16) {
        int gk = kb + k0 + lc;
        float4 va = (gk < XD1)
            ? *reinterpret_cast<const float4*>(X + (size_t)arow * XD1 + gk)
            : *reinterpret_cast<const float4*>(Hc + (size_t)arow * DD + (gk - XD1));
        float4 vw = *reinterpret_cast<const float4*>(g_Wcat + (size_t)wrow * XDIM + gk);
        STORE_A(va); STORE_W(vw);
        __syncthreads();
        tile_mma(sA, sW, ty4, tx4, acc);
        __syncthreads();
    }
    float* Cz = Cpart + (size_t)sk * (128 * GDIM);
#pragma unroll
    for (int i = 0; i < 4; i++) {
        int row = m0 + ty4 + i;
        float2 v0 = unpk(acc[i][0]), v1 = unpk(acc[i][1]);
        *reinterpret_cast<float4*>(Cz + (size_t)row * GDIM + n0 + tx4) =
            make_float4(v0.x, v0.y, v1.x, v1.y);
    }
}

// ---------------- small kernels ----------------
__global__ void mean_kernel(const float* __restrict__ img)
{
    int idx = blockIdx.x * blockDim.x + threadIdx.x;
    if (idx >= BB * CC) return;
    int b = idx / CC, c = idx % CC;
    const float* p = img + (size_t)b * NN * CC + c;
    float s = 0.f;
#pragma unroll 7
    for (int n = 0; n < NN; n++) s += p[(size_t)n * CC];
    g_mean[idx] = s * (1.0f / NN);
}

__global__ void hm_init_kernel()
{
    int idx = blockIdx.x * blockDim.x + threadIdx.x;
    if (idx >= BB * DD) return;
    int b = idx >> 9, d = idx & 511;
    g_h[0][idx] = g_vghm[b * 1536 + 512 + d];
    g_m[0][idx] = g_vghm[b * 1536 + 1024 + d];
}

__global__ void xall_init_kernel(const float* __restrict__ emb, const int* __restrict__ target)
{
    int idx = blockIdx.x * blockDim.x + threadIdx.x;
    if (idx >= TT * BB * XD1) return;
    int j = idx % XD1;
    int tb = idx / XD1;
    int b = tb % BB;
    int t = tb / BB;
    float v;
    if (j < 512) v = g_vghm[b * 1536 + j];          // vg
    else if (t == 0) v = 0.f;
    else {
        int tok = target[b * TT + t - 1];
        v = emb[(size_t)tok * EE + (j - 512)];
    }
    g_xall[((size_t)t * BB + b) * XD1 + j] = v;
}

__global__ void build_wcat_kernel(const float* __restrict__ Wih, const float* __restrict__ Whh,
                                  const float* __restrict__ Wx, const float* __restrict__ Wh2,
                                  const float* __restrict__ bih, const float* __restrict__ bhh)
{
    int idx = blockIdx.x * blockDim.x + threadIdx.x;
    if (idx >= GDIM * XDIM) return;
    int r = idx / XDIM, c = idx % XDIM;
    float v;
    if (r < 2048) v = (c < 1024) ? Wih[(size_t)r * 1024 + c] : Whh[(size_t)r * 512 + (c - 1024)];
    else {
        int r2 = r - 2048;
        v = (c < 1024) ? Wx[(size_t)r2 * 1024 + c] : Wh2[(size_t)r2 * 512 + (c - 1024)];
    }
    g_Wcat[idx] = v;
    if (c == 0) g_bcat[r] = (r < 2048) ? (bih[r] + bhh[r]) : 0.f;
}

// reduce split-K preact partials + bias, apply LSTM nonlinearity
__global__ void lstm_elem_kernel(int cur, int nxt)
{
    int idx = blockIdx.x * blockDim.x + threadIdx.x;
    if (idx >= BB * DD) return;
    int b = idx >> 9, d = idx & 511;
    float gi = g_bcat[d], gf = g_bcat[512 + d], gg = g_bcat[1024 + d],
          go = g_bcat[1536 + d], gl = g_bcat[2048 + d];
#pragma unroll
    for (int sk = 0; sk < SKP; sk++) {
        const float* p = g_pre_part[sk] + (size_t)b * GDIM;
        gi += p[d]; gf += p[512 + d]; gg += p[1024 + d]; go += p[1536 + d]; gl += p[2048 + d];
    }
    float m2 = sigf(gf) * g_m[cur][idx] + sigf(gi) * tanhf(gg);
    float tm2 = tanhf(m2);
    g_m[nxt][idx] = m2;
    g_h[nxt][idx] = sigf(go) * tm2;
    g_u[idx] = sigf(gl) * tm2;
}

// fused: reduce H/s partials, gH = H@Wg^T, sWs = s@Ws^T, z, z2, softmax(50), attn out, ctx, t1=H+ctx
__global__ void attn_fused_kernel(const float* __restrict__ Wg, const float* __restrict__ Wsm,
                                  const float* __restrict__ wh, const float* __restrict__ bc,
                                  float* __restrict__ attn_out, int t)
{
    int b = blockIdx.x;
    __shared__ float sH[512], sS[512];
    __shared__ float gHs[49], sWss[49], zsh[50], wsh[49];
    int tid = threadIdx.x;  // 256
    for (int j = tid; j < 512; j += 256) {
        float a = 0.f, c = bc[j];
#pragma unroll
        for (int sk = 0; sk < SKP; sk++) {
            a += g_hs_part[sk][b * 512 + j];
            c += g_hs_part[SKP + sk][b * 512 + j];
        }
        sH[j] = fmaxf(a, 0.f);
        sS[j] = fmaxf(c, 0.f);
    }
    if (tid < 49) wsh[tid] = wh[tid];
    __syncthreads();

    int w = tid >> 5, lane = tid & 31;
    for (int n = w; n < 49; n += 8) {
        float a = 0.f, c = 0.f;
        const float* wg = Wg + (size_t)n * 512;
        const float* ws = Wsm + (size_t)n * 512;
        for (int d = lane; d < 512; d += 32) {
            a = fmaf(sH[d], wg[d], a);
            c = fmaf(sS[d], ws[d], c);
        }
#pragma unroll
        for (int off = 16; off; off >>= 1) {
            a += __shfl_down_sync(0xffffffffu, a, off);
            c += __shfl_down_sync(0xffffffffu, c, off);
        }
        if (lane == 0) { gHs[n] = a; sWss[n] = c; }
    }
    __syncthreads();

    if (tid < 49) {
        const float* zb = g_zbase + ((size_t)b * 49 + tid) * 49;
        float acc = 0.f;
#pragma unroll 7
        for (int k = 0; k < 49; k++) acc += tanhf(zb[k] + gHs[k]) * wsh[k];
        zsh[tid] = acc;
    } else if (tid == 49) {
        float acc = 0.f;
#pragma unroll 7
        for (int k = 0; k < 49; k++) acc += tanhf(sWss[k] + gHs[k]) * wsh[k];
        zsh[49] = acc;
    }
    __syncthreads();

    if (tid == 0) {
        float mx = -1e30f;
        for (int i = 0; i < 50; i++) mx = fmaxf(mx, zsh[i]);
        float sum = 0.f;
        for (int i = 0; i < 50; i++) { zsh[i] = expf(zsh[i] - mx); sum += zsh[i]; }
        float inv = 1.f / sum;
        for (int i = 0; i < 50; i++) zsh[i] *= inv;
    }
    __syncthreads();

    if (tid < 49) attn_out[((size_t)b * TT + t) * 49 + tid] = zsh[tid];

    float a50 = zsh[49];
    for (int d = tid; d < 512; d += 256) {
        float acc = a50 * sS[d];
#pragma unroll 7
        for (int n = 0; n < 49; n++)
            acc = fmaf(zsh[n], g_Vf[((size_t)b * 49 + n) * 512 + d], acc);
        g_t1[b * 512 + d] = sH[d] + acc;
    }
}

// reduce Wfc split-K partials + bias + tanh
__global__ void reduce_fc_kernel(const float* __restrict__ bfc)
{
    int idx = blockIdx.x * blockDim.x + threadIdx.x;
    if (idx >= BB * DD) return;
    int d = idx & 511;
    float v = bfc[d];
#pragma unroll
    for (int sk = 0; sk < SKP; sk++) v += g_fc_part[sk][idx];
    g_o512[idx] = tanhf(v);
}

__global__ void log_softmax_kernel(float* __restrict__ logits)
{
    int row = blockIdx.x;  // B*T rows
    float* x = logits + (size_t)row * VV;
    __shared__ float red[256];
    int tid = threadIdx.x;
    float mx = -1e30f;
    for (int i = tid; i < VV; i += 256) mx = fmaxf(mx, x[i]);
    red[tid] = mx; __syncthreads();
    for (int s = 128; s; s >>= 1) { if (tid < s) red[tid] = fmaxf(red[tid], red[tid + s]); __syncthreads(); }
    mx = red[0];
    __syncthreads();
    float sum = 0.f;
    for (int i = tid; i < VV; i += 256) sum += expf(x[i] - mx);
    red[tid] = sum; __syncthreads();
    for (int s = 128; s; s >>= 1) { if (tid < s) red[tid] += red[tid + s]; __syncthreads(); }
    float lse = mx + logf(red[0]);
    for (int i = tid; i < VV; i += 256) x[i] -= lse;
}

// ---------------- host ----------------
static inline dim3 ggrid(int M, int N) { return dim3((N + 63) / 64, (M + 63) / 64); }

extern "C" void kernel_launch(void* const* d_in, const int* in_sizes, int n_in,
                              void* d_out, int out_size)
{
    const float* img    = (const float*)d_in[0];
    const int*   target = (const int*)d_in[1];
    const float* emb    = (const float*)d_in[2];
    const float* Wa  = (const float*)d_in[3];  const float* ba  = (const float*)d_in[4];
    const float* Wb  = (const float*)d_in[5];  const float* bb  = (const float*)d_in[6];
    const float* Whi = (const float*)d_in[7];  const float* bhi = (const float*)d_in[8];
    const float* Wmi = (const float*)d_in[9];  const float* bmi = (const float*)d_in[10];
    const float* Wih = (const float*)d_in[11]; const float* bih = (const float*)d_in[12];
    const float* Whh = (const float*)d_in[13]; const float* bhh = (const float*)d_in[14];
    const float* Wv  = (const float*)d_in[15];
    const float* Wg  = (const float*)d_in[16];
    const float* wh  = (const float*)d_in[17];
    const float* WH  = (const float*)d_in[18];
    const float* Wx  = (const float*)d_in[19];
    const float* Wh2 = (const float*)d_in[20];
    const float* Wsm = (const float*)d_in[21];
    const float* Wc  = (const float*)d_in[22]; const float* bc  = (const float*)d_in[23];
    const float* Wfc = (const float*)d_in[24]; const float* bfc = (const float*)d_in[25];
    const float* Wp  = (const float*)d_in[26]; const float* bp  = (const float*)d_in[27];

    float* out_logits = (float*)d_out;                               // [B,T,VOC]
    float* out_attn   = (float*)d_out + (size_t)BB * TT * VV;        // [B,T,N]

    float *p_mean, *p_vghm, *p_Vf, *p_xall, *p_Wbhm, *p_bbhm;
    float *p_pre, *p_hs, *p_fc, *p_h, *p_u, *p_t1, *p_o512, *p_zbase;
    cudaGetSymbolAddress((void**)&p_mean,  g_mean);
    cudaGetSymbolAddress((void**)&p_vghm,  g_vghm);
    cudaGetSymbolAddress((void**)&p_Vf,    g_Vf);
    cudaGetSymbolAddress((void**)&p_zbase, g_zbase);
    cudaGetSymbolAddress((void**)&p_xall,  g_xall);
    cudaGetSymbolAddress((void**)&p_Wbhm,  g_Wbhm);
    cudaGetSymbolAddress((void**)&p_bbhm,  g_bbhm);
    cudaGetSymbolAddress((void**)&p_pre,   g_pre_part);
    cudaGetSymbolAddress((void**)&p_hs,    g_hs_part);
    cudaGetSymbolAddress((void**)&p_fc,    g_fc_part);
    cudaGetSymbolAddress((void**)&p_h,     g_h);
    cudaGetSymbolAddress((void**)&p_u,     g_u);
    cudaGetSymbolAddress((void**)&p_t1,    g_t1);
    cudaGetSymbolAddress((void**)&p_o512,  g_o512);

    // ---- precompute ----
    const size_t WSZ = (size_t)DD * CC * sizeof(float);
    cudaMemcpyAsync(p_Wbhm,               Wb,  WSZ, cudaMemcpyDeviceToDevice);
    cudaMemcpyAsync(p_Wbhm + 512 * CC,    Whi, WSZ, cudaMemcpyDeviceToDevice);
    cudaMemcpyAsync(p_Wbhm + 1024 * CC,   Wmi, WSZ, cudaMemcpyDeviceToDevice);
    cudaMemcpyAsync(p_bbhm,        bb,  512 * sizeof(float), cudaMemcpyDeviceToDevice);
    cudaMemcpyAsync(p_bbhm + 512,  bhi, 512 * sizeof(float), cudaMemcpyDeviceToDevice);
    cudaMemcpyAsync(p_bbhm + 1024, bmi, 512 * sizeof(float), cudaMemcpyDeviceToDevice);

    mean_kernel<<<(BB * CC + 255) / 256, 256>>>(img);
    // [vg|h0|m0] = relu(mean @ Wbhm^T + bbhm)
    gemm_act<1><<<ggrid(BB, 1536), 256>>>(p_mean, CC, p_Wbhm, CC, p_bbhm, p_vghm, 1536, BB, 1536, CC);
    hm_init_kernel<<<(BB * DD + 255) / 256, 256>>>();
    // Vf = relu(img @ Wa^T + ba)
    gemm_act<1><<<ggrid(BB * NN, DD), 256>>>(img, CC, Wa, CC, ba, p_Vf, DD, BB * NN, DD, CC);
    // zbase = Vf @ Wv^T
    gemm_act<0><<<ggrid(BB * NN, NN), 256>>>(p_Vf, DD, Wv, DD, nullptr, p_zbase, NN, BB * NN, NN, DD);
    xall_init_kernel<<<(TT * BB * XD1 + 255) / 256, 256>>>(emb, target);
    build_wcat_kernel<<<(GDIM * XDIM + 255) / 256, 256>>>(Wih, Whh, Wx, Wh2, bih, bhh);

    // ---- timestep loop ----
    for (int t = 0; t < TT; t++) {
        int cur = t & 1, nxt = cur ^ 1;
        // preact partials: [x_t | h_cur] @ Wcat^T
        gemm_preact<<<dim3(GDIM / 64, 2, SKP), 256>>>(p_xall + (size_t)t * BB * XD1,
                                                      p_h + (size_t)cur * BB * DD, p_pre);
        lstm_elem_kernel<<<(BB * DD + 255) / 256, 256>>>(cur, nxt);
        // H & s partials in one launch: z = which*SKP + kslice
        gemm_sksel<<<dim3(8, 2, 2 * SKP), 256>>>(p_h + (size_t)nxt * BB * DD, p_u,
                                                 WH, Wc, p_hs, SKP);
        attn_fused_kernel<<<BB, 256>>>(Wg, Wsm, wh, bc, out_attn, t);
        // Wfc partials
        gemm_sksel<<<dim3(8, 2, SKP), 256>>>(p_t1, p_t1, Wfc, Wfc, p_fc, SKP);
        reduce_fc_kernel<<<(BB * DD + 255) / 256, 256>>>(bfc);
        // logits into d_out at [:, t, :]
        gemm_act<0><<<ggrid(BB, VV), 256>>>(p_o512, DD, Wp, DD, bp,
                                            out_logits + (size_t)t * VV, (long long)TT * VV,
                                            BB, VV, DD);
    }

    log_softmax_kernel<<<BB * TT, 256>>>(out_logits);
}